// round 2
// baseline (speedup 1.0000x reference)
#include <cuda_runtime.h>
#include <math.h>

#define K 64
#define D 64
#define STRIDE 66            // padded k-stride for transposed tiles (even -> 8B aligned pairs)
#define ROWS_PER_CTA 4
#define NTHREADS 256
#define ALPHA 0.2f
#define NEG_INF -9e15f
#define EPS 1e-8f

struct SmemT {
    float W1t[D * D];        // W1t[j][d] = fc_w[d][j]
    float W2t[D * D];        // W2t[j][d] = fc_w[d][64+j]
    float bias[D];
    float dstT[D * STRIDE];  // dstT[j][k] = dst[k][j]
    float relT[D * STRIDE];
    float gT[D * STRIDE];    // gT[d][k]  = g[k][d] = (W2 dst[k] + b)[d]
    float sS[D];
    float uS[D];
    float grS[K];            // g.rel
    float ggS[K];            // ||g||^2
    float rynS[K];           // max(||rel||, eps)
    float eS[K];             // logits -> exp(p)
    float pA[4 * 64];
    float pB[4 * 64];
    float red[8];
    int   mk[K];
};

typedef unsigned long long ull;

__device__ __forceinline__ ull pack2(float x, float y) {
    ull r;
    asm("mov.b64 %0, {%1, %2};" : "=l"(r) : "f"(x), "f"(y));
    return r;
}
__device__ __forceinline__ void ffma2(ull &d, ull a, ull b) {
    asm("fma.rn.f32x2 %0, %1, %2, %0;" : "+l"(d) : "l"(a), "l"(b));
}

__global__ void __launch_bounds__(NTHREADS, 2)
kgat_fused_kernel(const float* __restrict__ src,
                  const float* __restrict__ dst,
                  const float* __restrict__ rel,
                  const float* __restrict__ fcw,
                  const float* __restrict__ fcb,
                  const int*   __restrict__ mask,
                  float* __restrict__ out,
                  int N, int Nout)
{
    extern __shared__ __align__(16) char smem_raw[];
    SmemT* sm = reinterpret_cast<SmemT*>(smem_raw);

    const int t = threadIdx.x;
    const int w = t >> 5;
    const int l = t & 31;

    // ---- CTA init: transpose fc_w into W1t / W2t, load bias ----
    for (int idx = t; idx < D * 2 * D; idx += NTHREADS) {
        int dd = idx >> 7;         // row of fc_w (output dim)
        int f  = idx & 127;        // input-feature index
        float v = fcw[idx];
        if (f < 64) sm->W1t[f * D + dd] = v;
        else        sm->W2t[(f - 64) * D + dd] = v;
    }
    if (t < D) sm->bias[t] = fcb[t];
    __syncthreads();

    const int n0 = blockIdx.x * ROWS_PER_CTA;

    for (int r = 0; r < ROWS_PER_CTA; ++r) {
        const int n = n0 + r;
        if (n >= N) break;  // uniform per CTA

        // ================= Phase 1: loads (transposed) =================
        {
            const float* dg = dst + (size_t)n * (K * D);
            const float* rg = rel + (size_t)n * (K * D);
            // warp w handles k in [8w, 8w+8); coalesced 128B reads, 2-way-conflict STS
            float vd[16], vr[16];
            #pragma unroll
            for (int rr = 0; rr < 8; ++rr) {
                int k = w * 8 + rr;
                vd[2*rr]   = dg[k * D + l];
                vd[2*rr+1] = dg[k * D + 32 + l];
                vr[2*rr]   = rg[k * D + l];
                vr[2*rr+1] = rg[k * D + 32 + l];
            }
            #pragma unroll
            for (int rr = 0; rr < 8; ++rr) {
                int k = w * 8 + rr;
                sm->dstT[l * STRIDE + k]        = vd[2*rr];
                sm->dstT[(32 + l) * STRIDE + k] = vd[2*rr+1];
                sm->relT[l * STRIDE + k]        = vr[2*rr];
                sm->relT[(32 + l) * STRIDE + k] = vr[2*rr+1];
            }
            if (t < D) sm->sS[t] = src[(size_t)n * D + t];
        }
        __syncthreads();

        // ================= Phase 2: g GEMM (f32x2, k-pair packed) ======
        {
            const int dcol = (w & 1) * 32 + l;   // output feature d
            const int kb   = (w >> 1) * 16;      // k-block of 16 (8 pairs)
            const float bd = sm->bias[dcol];
            ull acc[8];
            const ull binit = pack2(bd, bd);
            #pragma unroll
            for (int m = 0; m < 8; ++m) acc[m] = binit;

            #pragma unroll 8
            for (int j = 0; j < D; ++j) {
                float wv = sm->W2t[j * D + dcol];
                ull ww = pack2(wv, wv);
                const float* drow = &sm->dstT[j * STRIDE + kb];
                #pragma unroll
                for (int m = 0; m < 8; ++m) {
                    ull dd = *reinterpret_cast<const ull*>(drow + 2 * m);
                    ffma2(acc[m], dd, ww);
                }
            }
            float* gout = &sm->gT[dcol * STRIDE + kb];
            #pragma unroll
            for (int m = 0; m < 8; ++m)
                *reinterpret_cast<ull*>(gout + 2 * m) = acc[m];
        }
        __syncthreads();

        // ================= Phase 3: per-k row stats ====================
        if (t < 64) {
            int k = t;
            float a = 0.f, b = 0.f;
            #pragma unroll 8
            for (int dd = 0; dd < D; ++dd) {
                float g = sm->gT[dd * STRIDE + k];
                float rv = sm->relT[dd * STRIDE + k];
                a += g * rv;
                b += g * g;
            }
            sm->grS[k] = a;
            sm->ggS[k] = b;
        } else if (t < 128) {
            int k = t - 64;
            float rn = 0.f;
            #pragma unroll 8
            for (int dd = 0; dd < D; ++dd) {
                float rv = sm->relT[dd * STRIDE + k];
                rn += rv * rv;
            }
            sm->rynS[k] = fmaxf(sqrtf(rn), EPS);
        } else if (t < 192) {
            sm->mk[t - 128] = mask[(size_t)n * K + (t - 128)];
        }
        __syncthreads();

        // ================= Two GAT layers =============================
        #pragma unroll 1
        for (int layer = 0; layer < 2; ++layer) {
            // ---- u = W1 s (partials across 4 groups) ----
            {
                int dd = t & 63, p = t >> 6;
                float a = 0.f;
                #pragma unroll
                for (int j = p * 16; j < p * 16 + 16; ++j)
                    a += sm->sS[j] * sm->W1t[j * D + dd];
                sm->pA[p * 64 + dd] = a;
            }
            __syncthreads();
            if (t < 64)
                sm->uS[t] = sm->pA[t] + sm->pA[64 + t] + sm->pA[128 + t] + sm->pA[192 + t];
            __syncthreads();
            // ---- uu = ||u||^2 ----
            if (t < 64) {
                float v = sm->uS[t] * sm->uS[t];
                #pragma unroll
                for (int o = 16; o > 0; o >>= 1)
                    v += __shfl_xor_sync(0xffffffffu, v, o);
                if ((t & 31) == 0) sm->red[t >> 5] = v;
            }
            __syncthreads();
            const float uu = sm->red[0] + sm->red[1];

            // ---- per-k: u.rel and u.g partials ----
            {
                int k = t & 63, p = t >> 6;
                float a = 0.f, c = 0.f;
                #pragma unroll
                for (int x = p * 16; x < p * 16 + 16; ++x) {
                    float uv = sm->uS[x];
                    a += uv * sm->relT[x * STRIDE + k];
                    c += uv * sm->gT[x * STRIDE + k];
                }
                sm->pA[p * 64 + k] = a;
                sm->pB[p * 64 + k] = c;
            }
            __syncthreads();
            if (t < 64) {
                int k = t;
                float ur = sm->pA[k] + sm->pA[64 + k] + sm->pA[128 + k] + sm->pA[192 + k];
                float ug = sm->pB[k] + sm->pB[64 + k] + sm->pB[128 + k] + sm->pB[192 + k];
                float hr = ur + sm->grS[k];
                float hh = uu + 2.f * ug + sm->ggS[k];
                float xn = sqrtf(fmaxf(hh, 0.f));
                float cs = hr / (fmaxf(xn, EPS) * sm->rynS[k]);
                float el = cs > 0.f ? cs : ALPHA * cs;
                sm->eS[k] = (sm->mk[k] > 0) ? el : NEG_INF;
            }
            __syncthreads();
            // ---- softmax over K (2-warp reduce) ----
            if (t < 64) {
                float m = sm->eS[t];
                #pragma unroll
                for (int o = 16; o > 0; o >>= 1)
                    m = fmaxf(m, __shfl_xor_sync(0xffffffffu, m, o));
                if ((t & 31) == 0) sm->red[t >> 5] = m;
            }
            __syncthreads();
            if (t < 64) {
                float M = fmaxf(sm->red[0], sm->red[1]);
                float p_ = __expf(sm->eS[t] - M);
                sm->eS[t] = p_;
                float s = p_;
                #pragma unroll
                for (int o = 16; o > 0; o >>= 1)
                    s += __shfl_xor_sync(0xffffffffu, s, o);
                if ((t & 31) == 0) sm->red[2 + (t >> 5)] = s;
            }
            __syncthreads();
            const float denom = sm->red[2] + sm->red[3];

            // ---- agg = sum_k att[k] * dst[k] (normalize at the end) ----
            {
                int dd = t & 63, p = t >> 6;
                float a = 0.f;
                #pragma unroll
                for (int k2 = p * 16; k2 < p * 16 + 16; ++k2)
                    a += sm->eS[k2] * sm->dstT[dd * STRIDE + k2];
                sm->pA[p * 64 + dd] = a;
            }
            __syncthreads();
            if (t < 64) {
                float agg = (sm->pA[t] + sm->pA[64 + t] + sm->pA[128 + t] + sm->pA[192 + t]) / denom;
                float o = agg + sm->sS[t];
                if (layer == 0) {
                    sm->sS[t] = o;           // feed layer 2
                } else if (n < Nout) {
                    out[(size_t)n * D + t] = o;
                }
            }
            __syncthreads();
        }
    }
}

extern "C" void kernel_launch(void* const* d_in, const int* in_sizes, int n_in,
                              void* d_out, int out_size)
{
    const float* src = (const float*)d_in[0];
    const float* dst = (const float*)d_in[1];
    const float* rel = (const float*)d_in[2];
    const float* fcw = (const float*)d_in[3];
    const float* fcb = (const float*)d_in[4];
    const int*   msk = (const int*)d_in[5];
    float* out = (float*)d_out;

    const int N = in_sizes[0] / D;
    const int Nout = out_size / D;

    const int smem_bytes = (int)sizeof(SmemT);
    cudaFuncSetAttribute(kgat_fused_kernel,
                         cudaFuncAttributeMaxDynamicSharedMemorySize, smem_bytes);

    const int blocks = (N + ROWS_PER_CTA - 1) / ROWS_PER_CTA;
    kgat_fused_kernel<<<blocks, NTHREADS, smem_bytes>>>(src, dst, rel, fcw, fcb,
                                                        msk, out, N, Nout);
}